// round 12
// baseline (speedup 1.0000x reference)
#include <cuda_runtime.h>
#include <math.h>

#define BB   2
#define TT   2048
#define DD   2048
#define HH   16
#define HD   128
#define SCALE 0.08838834764831845f   // 1/sqrt(128)

// ---------------- scratch (allocation-free: __device__ globals) ----------------
__device__ float g_Q[BB * TT * DD];
__device__ float g_K[BB * TT * DD];
__device__ float g_V[BB * TT * DD];
__device__ float g_O[BB * TT * DD];

// =====================================================================
// Tiled NT SGEMM body: C[m][n] = sum_k A[m][k] * W[n][k] + bias[n]
// M x N tiles of 128x128, BK=16, 256 threads, 8x8 micro-tile.
// =====================================================================
__device__ __forceinline__
void gemm_body(const float* __restrict__ A, const float* __restrict__ W,
               const float* __restrict__ bias, float* __restrict__ C)
{
    __shared__ float As[16 * 132];
    __shared__ float Bs[16 * 132];

    const int tid = threadIdx.x;
    const int tx = tid & 15;        // 0..15  -> cols tx*8 .. tx*8+7
    const int ty = tid >> 4;        // 0..15  -> rows ty*8 .. ty*8+7
    const int m0 = blockIdx.y * 128;
    const int n0 = blockIdx.x * 128;
    const int K  = DD;
    const int N  = DD;

    float acc[8][8];
#pragma unroll
    for (int i = 0; i < 8; ++i)
#pragma unroll
        for (int j = 0; j < 8; ++j) acc[i][j] = 0.f;

    for (int k0 = 0; k0 < K; k0 += 16) {
        __syncthreads();
        // A tile 128x16 -> As[k][m]   (512 float4 slots, 2 per thread)
#pragma unroll
        for (int p = tid; p < 512; p += 256) {
            int row = p >> 2, c4 = (p & 3) * 4;
            float4 v = *(const float4*)(A + (size_t)(m0 + row) * K + k0 + c4);
            As[(c4 + 0) * 132 + row] = v.x;
            As[(c4 + 1) * 132 + row] = v.y;
            As[(c4 + 2) * 132 + row] = v.z;
            As[(c4 + 3) * 132 + row] = v.w;
        }
        // W tile 128x16 -> Bs[k][n]
#pragma unroll
        for (int p = tid; p < 512; p += 256) {
            int row = p >> 2, c4 = (p & 3) * 4;
            float4 v = *(const float4*)(W + (size_t)(n0 + row) * K + k0 + c4);
            Bs[(c4 + 0) * 132 + row] = v.x;
            Bs[(c4 + 1) * 132 + row] = v.y;
            Bs[(c4 + 2) * 132 + row] = v.z;
            Bs[(c4 + 3) * 132 + row] = v.w;
        }
        __syncthreads();
#pragma unroll
        for (int k = 0; k < 16; ++k) {
            float a[8], b[8];
            *(float4*)(a)     = *(const float4*)&As[k * 132 + ty * 8];
            *(float4*)(a + 4) = *(const float4*)&As[k * 132 + ty * 8 + 4];
            *(float4*)(b)     = *(const float4*)&Bs[k * 132 + tx * 8];
            *(float4*)(b + 4) = *(const float4*)&Bs[k * 132 + tx * 8 + 4];
#pragma unroll
            for (int i = 0; i < 8; ++i)
#pragma unroll
                for (int j = 0; j < 8; ++j)
                    acc[i][j] += a[i] * b[j];
        }
    }

    // epilogue: add bias, vectorized store
#pragma unroll
    for (int i = 0; i < 8; ++i) {
        int m = m0 + ty * 8 + i;
#pragma unroll
        for (int j = 0; j < 8; j += 4) {
            int n = n0 + tx * 8 + j;
            float4 bv = *(const float4*)(bias + n);
            float4 o;
            o.x = acc[i][j + 0] + bv.x;
            o.y = acc[i][j + 1] + bv.y;
            o.z = acc[i][j + 2] + bv.z;
            o.w = acc[i][j + 3] + bv.w;
            *(float4*)(C + (size_t)m * N + n) = o;
        }
    }
}

// QKV projections: gridDim.z selects which of Q/K/V
__global__ __launch_bounds__(256, 2)
void qkv_gemm(const float* __restrict__ X,
              const float* __restrict__ Wq, const float* __restrict__ bq,
              const float* __restrict__ Wk, const float* __restrict__ bk,
              const float* __restrict__ Wv, const float* __restrict__ bv)
{
    const float* W; const float* bias; float* C;
    if (blockIdx.z == 0)      { W = Wq; bias = bq; C = g_Q; }
    else if (blockIdx.z == 1) { W = Wk; bias = bk; C = g_K; }
    else                      { W = Wv; bias = bv; C = g_V; }
    gemm_body(X, W, bias, C);
}

// Output projection: out = g_O @ Wo^T + bo
__global__ __launch_bounds__(256, 2)
void out_gemm(const float* __restrict__ Wo, const float* __restrict__ bo,
              float* __restrict__ out)
{
    gemm_body(g_O, Wo, bo, out);
}

// =====================================================================
// Flash attention (fp32, causal).
// One block = one (b,h) and 128 query rows. 256 threads.
// Inner loop over 64-key tiles: S = Q K^T (staged over HD in 16-chunks),
// online softmax in registers (16-lane shuffle row reductions),
// P staged through smem, O += P V.
// =====================================================================
#define ATTN_SMEM_FLOATS (16*132 + 16*68 + 128*68 + 64*128)
#define ATTN_SMEM_BYTES  (ATTN_SMEM_FLOATS * 4)

__global__ __launch_bounds__(256, 1)
void attn_kernel()
{
    extern __shared__ float sm[];
    float* Qs = sm;                        // [16][132]
    float* Ks = Qs + 16 * 132;             // [16][68]
    float* Ps = Ks + 16 * 68;              // [128][68]
    float* Vs = Ps + 128 * 68;             // [64][128]

    const int tid = threadIdx.x;
    const int tx = tid & 15;               // key/HD column group
    const int ty = tid >> 4;               // query row group
    const int qt = gridDim.x - 1 - blockIdx.x;   // heaviest tiles launch first
    const int q0 = qt * 128;
    const int bh = blockIdx.y;
    const int b  = bh >> 4;
    const int h  = bh & 15;

    const float* Qg = g_Q + (size_t)b * TT * DD + h * HD;
    const float* Kg = g_K + (size_t)b * TT * DD + h * HD;
    const float* Vg = g_V + (size_t)b * TT * DD + h * HD;
    float*       Og = g_O + (size_t)b * TT * DD + h * HD;

    float o[8][8];
    float mrow[8], lrow[8];
#pragma unroll
    for (int i = 0; i < 8; ++i) {
        mrow[i] = -1e30f; lrow[i] = 0.f;
#pragma unroll
        for (int j = 0; j < 8; ++j) o[i][j] = 0.f;
    }

    const int ntiles = q0 / 64 + 2;        // causal: keys 0 .. q0+127
    for (int kt = 0; kt < ntiles; ++kt) {
        const int k0 = kt * 64;
        float s[8][4];
#pragma unroll
        for (int i = 0; i < 8; ++i)
#pragma unroll
            for (int j = 0; j < 4; ++j) s[i][j] = 0.f;

        // ---- GEMM1: S[128][64] = Q(q0:,:) * K(k0:,:)^T over HD=128 ----
        for (int d0 = 0; d0 < HD; d0 += 16) {
            __syncthreads();
            // Q tile 128x16 -> Qs[d][r]
#pragma unroll
            for (int p = tid; p < 512; p += 256) {
                int row = p >> 2, c4 = (p & 3) * 4;
                float4 v = *(const float4*)(Qg + (size_t)(q0 + row) * DD + d0 + c4);
                Qs[(c4 + 0) * 132 + row] = v.x;
                Qs[(c4 + 1) * 132 + row] = v.y;
                Qs[(c4 + 2) * 132 + row] = v.z;
                Qs[(c4 + 3) * 132 + row] = v.w;
            }
            // K tile 64x16 -> Ks[d][k]  (256 float4 slots, 1 per thread)
            {
                int row = tid >> 2, c4 = (tid & 3) * 4;
                float4 v = *(const float4*)(Kg + (size_t)(k0 + row) * DD + d0 + c4);
                Ks[(c4 + 0) * 68 + row] = v.x;
                Ks[(c4 + 1) * 68 + row] = v.y;
                Ks[(c4 + 2) * 68 + row] = v.z;
                Ks[(c4 + 3) * 68 + row] = v.w;
            }
            __syncthreads();
#pragma unroll
            for (int k = 0; k < 16; ++k) {
                float a[8], bb[4];
                *(float4*)(a)     = *(const float4*)&Qs[k * 132 + ty * 8];
                *(float4*)(a + 4) = *(const float4*)&Qs[k * 132 + ty * 8 + 4];
                *(float4*)(bb)    = *(const float4*)&Ks[k * 68 + tx * 4];
#pragma unroll
                for (int i = 0; i < 8; ++i)
#pragma unroll
                    for (int j = 0; j < 4; ++j)
                        s[i][j] += a[i] * bb[j];
            }
        }

        // ---- scale + causal mask + online softmax ----
        const bool need_mask = (k0 + 63 > q0);
        float alpha[8];
#pragma unroll
        for (int i = 0; i < 8; ++i) {
            const int gr = q0 + ty * 8 + i;
            float tm = -1e30f;
#pragma unroll
            for (int j = 0; j < 4; ++j) {
                float v = s[i][j] * SCALE;
                if (need_mask && (k0 + tx * 4 + j > gr)) v = -1e30f;
                s[i][j] = v;
                tm = fmaxf(tm, v);
            }
#pragma unroll
            for (int off = 1; off < 16; off <<= 1)
                tm = fmaxf(tm, __shfl_xor_sync(0xffffffffu, tm, off));
            const float mn = fmaxf(mrow[i], tm);
            const float al = __expf(mrow[i] - mn);
            float rs = 0.f;
#pragma unroll
            for (int j = 0; j < 4; ++j) {
                float p = __expf(s[i][j] - mn);
                s[i][j] = p;
                rs += p;
            }
#pragma unroll
            for (int off = 1; off < 16; off <<= 1)
                rs += __shfl_xor_sync(0xffffffffu, rs, off);
            lrow[i]  = lrow[i] * al + rs;
            mrow[i]  = mn;
            alpha[i] = al;
        }
#pragma unroll
        for (int i = 0; i < 8; ++i)
#pragma unroll
            for (int j = 0; j < 8; ++j)
                o[i][j] *= alpha[i];

        // ---- stage P to smem, load V tile ----
        // WAR on Ps/Vs vs previous tile's GEMM2 is protected by the barriers
        // inside this tile's GEMM1 loop above.
#pragma unroll
        for (int i = 0; i < 8; ++i) {
            float4 pv = make_float4(s[i][0], s[i][1], s[i][2], s[i][3]);
            *(float4*)&Ps[(ty * 8 + i) * 68 + tx * 4] = pv;
        }
#pragma unroll
        for (int p = tid; p < 2048; p += 256) {
            int row = p >> 5, c = (p & 31) * 4;
            float4 v = *(const float4*)(Vg + (size_t)(k0 + row) * DD + c);
            *(float4*)&Vs[row * 128 + c] = v;
        }
        __syncthreads();

        // ---- GEMM2: O[128][128] += P[128][64] * V[64][128] ----
#pragma unroll 4
        for (int kk = 0; kk < 64; ++kk) {
            float a[8];
#pragma unroll
            for (int i = 0; i < 8; ++i) a[i] = Ps[(ty * 8 + i) * 68 + kk];
            float bb[8];
            *(float4*)(bb)     = *(const float4*)&Vs[kk * 128 + tx * 8];
            *(float4*)(bb + 4) = *(const float4*)&Vs[kk * 128 + tx * 8 + 4];
#pragma unroll
            for (int i = 0; i < 8; ++i)
#pragma unroll
                for (int j = 0; j < 8; ++j)
                    o[i][j] += a[i] * bb[j];
        }
    }

    // ---- normalize + write O in [B,T,H,HD] (== [B,T,D]) layout ----
#pragma unroll
    for (int i = 0; i < 8; ++i) {
        const float inv = 1.f / lrow[i];
        const int gr = q0 + ty * 8 + i;
#pragma unroll
        for (int j = 0; j < 8; j += 4) {
            float4 v = make_float4(o[i][j] * inv, o[i][j + 1] * inv,
                                   o[i][j + 2] * inv, o[i][j + 3] * inv);
            *(float4*)(Og + (size_t)gr * DD + tx * 8 + j) = v;
        }
    }
}

// =====================================================================
// Launch
// =====================================================================
extern "C" void kernel_launch(void* const* d_in, const int* in_sizes, int n_in,
                              void* d_out, int out_size)
{
    const float* x  = (const float*)d_in[0];
    // d_in[1] = mask (causal by construction; not needed)
    const float* wq = (const float*)d_in[2];
    const float* bq = (const float*)d_in[3];
    const float* wk = (const float*)d_in[4];
    const float* bk = (const float*)d_in[5];
    const float* wv = (const float*)d_in[6];
    const float* bv = (const float*)d_in[7];
    const float* wo = (const float*)d_in[8];
    const float* bo = (const float*)d_in[9];
    float* out = (float*)d_out;

    // opt-in to >48KB dynamic smem (idempotent, host-side, capture-safe)
    cudaFuncSetAttribute(attn_kernel,
                         cudaFuncAttributeMaxDynamicSharedMemorySize,
                         ATTN_SMEM_BYTES);

    // 1) Q/K/V projections
    dim3 g1(DD / 128, (BB * TT) / 128, 3);
    qkv_gemm<<<g1, 256>>>(x, wq, bq, wk, bk, wv, bv);

    // 2) causal flash attention
    dim3 g2(TT / 128, BB * HH);
    attn_kernel<<<g2, 256, ATTN_SMEM_BYTES>>>();

    // 3) output projection
    dim3 g3(DD / 128, (BB * TT) / 128);
    out_gemm<<<g3, 256>>>(wo, bo, out);
}

// round 13
// speedup vs baseline: 1.0535x; 1.0535x over previous
#include <cuda_runtime.h>
#include <math.h>

#define BB   2
#define TT   2048
#define DD   2048
#define HH   16
#define HD   128
#define SCALE 0.08838834764831845f   // 1/sqrt(128)

// ---------------- scratch (allocation-free: __device__ globals) ----------------
__device__ float g_Q[BB * TT * DD];
__device__ float g_K[BB * TT * DD];
__device__ float g_V[BB * TT * DD];
__device__ float g_O[BB * TT * DD];

// =====================================================================
// Tiled NT SGEMM body: C[m][n] = sum_k A[m][k] * W[n][k] + bias[n]
// M x N tiles of 128x128, BK=16, 256 threads, 8x8 micro-tile.
// =====================================================================
__device__ __forceinline__
void gemm_body(const float* __restrict__ A, const float* __restrict__ W,
               const float* __restrict__ bias, float* __restrict__ C)
{
    __shared__ float As[16 * 132];
    __shared__ float Bs[16 * 132];

    const int tid = threadIdx.x;
    const int tx = tid & 15;        // 0..15  -> cols tx*8 .. tx*8+7
    const int ty = tid >> 4;        // 0..15  -> rows ty*8 .. ty*8+7
    const int m0 = blockIdx.y * 128;
    const int n0 = blockIdx.x * 128;
    const int K  = DD;
    const int N  = DD;

    float acc[8][8];
#pragma unroll
    for (int i = 0; i < 8; ++i)
#pragma unroll
        for (int j = 0; j < 8; ++j) acc[i][j] = 0.f;

    for (int k0 = 0; k0 < K; k0 += 16) {
        __syncthreads();
        // A tile 128x16 -> As[k][m]   (512 float4 slots, 2 per thread)
#pragma unroll
        for (int p = tid; p < 512; p += 256) {
            int row = p >> 2, c4 = (p & 3) * 4;
            float4 v = *(const float4*)(A + (size_t)(m0 + row) * K + k0 + c4);
            As[(c4 + 0) * 132 + row] = v.x;
            As[(c4 + 1) * 132 + row] = v.y;
            As[(c4 + 2) * 132 + row] = v.z;
            As[(c4 + 3) * 132 + row] = v.w;
        }
        // W tile 128x16 -> Bs[k][n]
#pragma unroll
        for (int p = tid; p < 512; p += 256) {
            int row = p >> 2, c4 = (p & 3) * 4;
            float4 v = *(const float4*)(W + (size_t)(n0 + row) * K + k0 + c4);
            Bs[(c4 + 0) * 132 + row] = v.x;
            Bs[(c4 + 1) * 132 + row] = v.y;
            Bs[(c4 + 2) * 132 + row] = v.z;
            Bs[(c4 + 3) * 132 + row] = v.w;
        }
        __syncthreads();
#pragma unroll
        for (int k = 0; k < 16; ++k) {
            float a[8], b[8];
            *(float4*)(a)     = *(const float4*)&As[k * 132 + ty * 8];
            *(float4*)(a + 4) = *(const float4*)&As[k * 132 + ty * 8 + 4];
            *(float4*)(b)     = *(const float4*)&Bs[k * 132 + tx * 8];
            *(float4*)(b + 4) = *(const float4*)&Bs[k * 132 + tx * 8 + 4];
#pragma unroll
            for (int i = 0; i < 8; ++i)
#pragma unroll
                for (int j = 0; j < 8; ++j)
                    acc[i][j] += a[i] * b[j];
        }
    }

    // epilogue: add bias, vectorized store
#pragma unroll
    for (int i = 0; i < 8; ++i) {
        int m = m0 + ty * 8 + i;
#pragma unroll
        for (int j = 0; j < 8; j += 4) {
            int n = n0 + tx * 8 + j;
            float4 bv = *(const float4*)(bias + n);
            float4 o;
            o.x = acc[i][j + 0] + bv.x;
            o.y = acc[i][j + 1] + bv.y;
            o.z = acc[i][j + 2] + bv.z;
            o.w = acc[i][j + 3] + bv.w;
            *(float4*)(C + (size_t)m * N + n) = o;
        }
    }
}

// QKV projections: gridDim.z selects which of Q/K/V
__global__ __launch_bounds__(256, 2)
void qkv_gemm(const float* __restrict__ X,
              const float* __restrict__ Wq, const float* __restrict__ bq,
              const float* __restrict__ Wk, const float* __restrict__ bk,
              const float* __restrict__ Wv, const float* __restrict__ bv)
{
    const float* W; const float* bias; float* C;
    if (blockIdx.z == 0)      { W = Wq; bias = bq; C = g_Q; }
    else if (blockIdx.z == 1) { W = Wk; bias = bk; C = g_K; }
    else                      { W = Wv; bias = bv; C = g_V; }
    gemm_body(X, W, bias, C);
}

// Output projection: out = g_O @ Wo^T + bo
__global__ __launch_bounds__(256, 2)
void out_gemm(const float* __restrict__ Wo, const float* __restrict__ bo,
              float* __restrict__ out)
{
    gemm_body(g_O, Wo, bo, out);
}

// =====================================================================
// Flash attention (fp32, causal).
// One block = one (b,h) and 128 query rows. 256 threads.
// Inner loop over 64-key tiles: S = Q K^T (staged over HD in 16-chunks),
// online softmax in registers (16-lane shuffle row reductions),
// P staged through smem, O += P V.
// =====================================================================
#define ATTN_SMEM_FLOATS (16*132 + 16*68 + 128*68 + 64*128)
#define ATTN_SMEM_BYTES  (ATTN_SMEM_FLOATS * 4)

__global__ __launch_bounds__(256, 1)
void attn_kernel()
{
    extern __shared__ float sm[];
    float* Qs = sm;                        // [16][132]
    float* Ks = Qs + 16 * 132;             // [16][68]
    float* Ps = Ks + 16 * 68;              // [128][68]
    float* Vs = Ps + 128 * 68;             // [64][128]

    const int tid = threadIdx.x;
    const int tx = tid & 15;               // key/HD column group
    const int ty = tid >> 4;               // query row group
    const int qt = gridDim.x - 1 - blockIdx.x;   // heaviest tiles launch first
    const int q0 = qt * 128;
    const int bh = blockIdx.y;
    const int b  = bh >> 4;
    const int h  = bh & 15;

    const float* Qg = g_Q + (size_t)b * TT * DD + h * HD;
    const float* Kg = g_K + (size_t)b * TT * DD + h * HD;
    const float* Vg = g_V + (size_t)b * TT * DD + h * HD;
    float*       Og = g_O + (size_t)b * TT * DD + h * HD;

    float o[8][8];
    float mrow[8], lrow[8];
#pragma unroll
    for (int i = 0; i < 8; ++i) {
        mrow[i] = -1e30f; lrow[i] = 0.f;
#pragma unroll
        for (int j = 0; j < 8; ++j) o[i][j] = 0.f;
    }

    const int ntiles = q0 / 64 + 2;        // causal: keys 0 .. q0+127
    for (int kt = 0; kt < ntiles; ++kt) {
        const int k0 = kt * 64;
        float s[8][4];
#pragma unroll
        for (int i = 0; i < 8; ++i)
#pragma unroll
            for (int j = 0; j < 4; ++j) s[i][j] = 0.f;

        // ---- GEMM1: S[128][64] = Q(q0:,:) * K(k0:,:)^T over HD=128 ----
        for (int d0 = 0; d0 < HD; d0 += 16) {
            __syncthreads();
            // Q tile 128x16 -> Qs[d][r]
#pragma unroll
            for (int p = tid; p < 512; p += 256) {
                int row = p >> 2, c4 = (p & 3) * 4;
                float4 v = *(const float4*)(Qg + (size_t)(q0 + row) * DD + d0 + c4);
                Qs[(c4 + 0) * 132 + row] = v.x;
                Qs[(c4 + 1) * 132 + row] = v.y;
                Qs[(c4 + 2) * 132 + row] = v.z;
                Qs[(c4 + 3) * 132 + row] = v.w;
            }
            // K tile 64x16 -> Ks[d][k]  (256 float4 slots, 1 per thread)
            {
                int row = tid >> 2, c4 = (tid & 3) * 4;
                float4 v = *(const float4*)(Kg + (size_t)(k0 + row) * DD + d0 + c4);
                Ks[(c4 + 0) * 68 + row] = v.x;
                Ks[(c4 + 1) * 68 + row] = v.y;
                Ks[(c4 + 2) * 68 + row] = v.z;
                Ks[(c4 + 3) * 68 + row] = v.w;
            }
            __syncthreads();
#pragma unroll
            for (int k = 0; k < 16; ++k) {
                float a[8], bb[4];
                *(float4*)(a)     = *(const float4*)&Qs[k * 132 + ty * 8];
                *(float4*)(a + 4) = *(const float4*)&Qs[k * 132 + ty * 8 + 4];
                *(float4*)(bb)    = *(const float4*)&Ks[k * 68 + tx * 4];
#pragma unroll
                for (int i = 0; i < 8; ++i)
#pragma unroll
                    for (int j = 0; j < 4; ++j)
                        s[i][j] += a[i] * bb[j];
            }
        }

        // ---- scale + causal mask + online softmax ----
        const bool need_mask = (k0 + 63 > q0);
        float alpha[8];
#pragma unroll
        for (int i = 0; i < 8; ++i) {
            const int gr = q0 + ty * 8 + i;
            float tm = -1e30f;
#pragma unroll
            for (int j = 0; j < 4; ++j) {
                float v = s[i][j] * SCALE;
                if (need_mask && (k0 + tx * 4 + j > gr)) v = -1e30f;
                s[i][j] = v;
                tm = fmaxf(tm, v);
            }
#pragma unroll
            for (int off = 1; off < 16; off <<= 1)
                tm = fmaxf(tm, __shfl_xor_sync(0xffffffffu, tm, off));
            const float mn = fmaxf(mrow[i], tm);
            const float al = __expf(mrow[i] - mn);
            float rs = 0.f;
#pragma unroll
            for (int j = 0; j < 4; ++j) {
                float p = __expf(s[i][j] - mn);
                s[i][j] = p;
                rs += p;
            }
#pragma unroll
            for (int off = 1; off < 16; off <<= 1)
                rs += __shfl_xor_sync(0xffffffffu, rs, off);
            lrow[i]  = lrow[i] * al + rs;
            mrow[i]  = mn;
            alpha[i] = al;
        }
#pragma unroll
        for (int i = 0; i < 8; ++i)
#pragma unroll
            for (int j = 0; j < 8; ++j)
                o[i][j] *= alpha[i];

        // ---- stage P to smem, load V tile ----
        // WAR on Ps/Vs vs previous tile's GEMM2 is protected by the barriers
        // inside this tile's GEMM1 loop above.
#pragma unroll
        for (int i = 0; i < 8; ++i) {
            float4 pv = make_float4(s[i][0], s[i][1], s[i][2], s[i][3]);
            *(float4*)&Ps[(ty * 8 + i) * 68 + tx * 4] = pv;
        }
#pragma unroll
        for (int p = tid; p < 2048; p += 256) {
            int row = p >> 5, c = (p & 31) * 4;
            float4 v = *(const float4*)(Vg + (size_t)(k0 + row) * DD + c);
            *(float4*)&Vs[row * 128 + c] = v;
        }
        __syncthreads();

        // ---- GEMM2: O[128][128] += P[128][64] * V[64][128] ----
#pragma unroll 4
        for (int kk = 0; kk < 64; ++kk) {
            float a[8];
#pragma unroll
            for (int i = 0; i < 8; ++i) a[i] = Ps[(ty * 8 + i) * 68 + kk];
            float bb[8];
            *(float4*)(bb)     = *(const float4*)&Vs[kk * 128 + tx * 8];
            *(float4*)(bb + 4) = *(const float4*)&Vs[kk * 128 + tx * 8 + 4];
#pragma unroll
            for (int i = 0; i < 8; ++i)
#pragma unroll
                for (int j = 0; j < 8; ++j)
                    o[i][j] += a[i] * bb[j];
        }
    }

    // ---- normalize + write O in [B,T,H,HD] (== [B,T,D]) layout ----
#pragma unroll
    for (int i = 0; i < 8; ++i) {
        const float inv = 1.f / lrow[i];
        const int gr = q0 + ty * 8 + i;
#pragma unroll
        for (int j = 0; j < 8; j += 4) {
            float4 v = make_float4(o[i][j] * inv, o[i][j + 1] * inv,
                                   o[i][j + 2] * inv, o[i][j + 3] * inv);
            *(float4*)(Og + (size_t)gr * DD + tx * 8 + j) = v;
        }
    }
}

// =====================================================================
// Launch
// =====================================================================
extern "C" void kernel_launch(void* const* d_in, const int* in_sizes, int n_in,
                              void* d_out, int out_size)
{
    const float* x  = (const float*)d_in[0];
    // d_in[1] = mask (causal by construction; not needed)
    const float* wq = (const float*)d_in[2];
    const float* bq = (const float*)d_in[3];
    const float* wk = (const float*)d_in[4];
    const float* bk = (const float*)d_in[5];
    const float* wv = (const float*)d_in[6];
    const float* bv = (const float*)d_in[7];
    const float* wo = (const float*)d_in[8];
    const float* bo = (const float*)d_in[9];
    float* out = (float*)d_out;

    // opt-in to >48KB dynamic smem (idempotent, host-side, capture-safe)
    cudaFuncSetAttribute(attn_kernel,
                         cudaFuncAttributeMaxDynamicSharedMemorySize,
                         ATTN_SMEM_BYTES);

    // 1) Q/K/V projections
    dim3 g1(DD / 128, (BB * TT) / 128, 3);
    qkv_gemm<<<g1, 256>>>(x, wq, bq, wk, bk, wv, bv);

    // 2) causal flash attention
    dim3 g2(TT / 128, BB * HH);
    attn_kernel<<<g2, 256, ATTN_SMEM_BYTES>>>();

    // 3) output projection
    dim3 g3(DD / 128, (BB * TT) / 128);
    out_gemm<<<g3, 256>>>(wo, bo, out);
}

// round 14
// speedup vs baseline: 1.0537x; 1.0002x over previous
#include <cuda_runtime.h>
#include <math.h>

#define BB   2
#define TT   2048
#define DD   2048
#define HH   16
#define HD   128
#define SCALE 0.08838834764831845f   // 1/sqrt(128)

// ---------------- scratch (allocation-free: __device__ globals) ----------------
__device__ float g_Q[BB * TT * DD];
__device__ float g_K[BB * TT * DD];
__device__ float g_V[BB * TT * DD];
__device__ float g_O[BB * TT * DD];

// =====================================================================
// Tiled NT SGEMM body: C[m][n] = sum_k A[m][k] * W[n][k] + bias[n]
// M x N tiles of 128x128, BK=16, 256 threads, 8x8 micro-tile.
// =====================================================================
__device__ __forceinline__
void gemm_body(const float* __restrict__ A, const float* __restrict__ W,
               const float* __restrict__ bias, float* __restrict__ C)
{
    __shared__ float As[16 * 132];
    __shared__ float Bs[16 * 132];

    const int tid = threadIdx.x;
    const int tx = tid & 15;        // 0..15  -> cols tx*8 .. tx*8+7
    const int ty = tid >> 4;        // 0..15  -> rows ty*8 .. ty*8+7
    const int m0 = blockIdx.y * 128;
    const int n0 = blockIdx.x * 128;
    const int K  = DD;
    const int N  = DD;

    float acc[8][8];
#pragma unroll
    for (int i = 0; i < 8; ++i)
#pragma unroll
        for (int j = 0; j < 8; ++j) acc[i][j] = 0.f;

    for (int k0 = 0; k0 < K; k0 += 16) {
        __syncthreads();
        // A tile 128x16 -> As[k][m]   (512 float4 slots, 2 per thread)
#pragma unroll
        for (int p = tid; p < 512; p += 256) {
            int row = p >> 2, c4 = (p & 3) * 4;
            float4 v = *(const float4*)(A + (size_t)(m0 + row) * K + k0 + c4);
            As[(c4 + 0) * 132 + row] = v.x;
            As[(c4 + 1) * 132 + row] = v.y;
            As[(c4 + 2) * 132 + row] = v.z;
            As[(c4 + 3) * 132 + row] = v.w;
        }
        // W tile 128x16 -> Bs[k][n]
#pragma unroll
        for (int p = tid; p < 512; p += 256) {
            int row = p >> 2, c4 = (p & 3) * 4;
            float4 v = *(const float4*)(W + (size_t)(n0 + row) * K + k0 + c4);
            Bs[(c4 + 0) * 132 + row] = v.x;
            Bs[(c4 + 1) * 132 + row] = v.y;
            Bs[(c4 + 2) * 132 + row] = v.z;
            Bs[(c4 + 3) * 132 + row] = v.w;
        }
        __syncthreads();
#pragma unroll
        for (int k = 0; k < 16; ++k) {
            float a[8], b[8];
            *(float4*)(a)     = *(const float4*)&As[k * 132 + ty * 8];
            *(float4*)(a + 4) = *(const float4*)&As[k * 132 + ty * 8 + 4];
            *(float4*)(b)     = *(const float4*)&Bs[k * 132 + tx * 8];
            *(float4*)(b + 4) = *(const float4*)&Bs[k * 132 + tx * 8 + 4];
#pragma unroll
            for (int i = 0; i < 8; ++i)
#pragma unroll
                for (int j = 0; j < 8; ++j)
                    acc[i][j] += a[i] * b[j];
        }
    }

    // epilogue: add bias, vectorized store
#pragma unroll
    for (int i = 0; i < 8; ++i) {
        int m = m0 + ty * 8 + i;
#pragma unroll
        for (int j = 0; j < 8; j += 4) {
            int n = n0 + tx * 8 + j;
            float4 bv = *(const float4*)(bias + n);
            float4 o;
            o.x = acc[i][j + 0] + bv.x;
            o.y = acc[i][j + 1] + bv.y;
            o.z = acc[i][j + 2] + bv.z;
            o.w = acc[i][j + 3] + bv.w;
            *(float4*)(C + (size_t)m * N + n) = o;
        }
    }
}

// QKV projections: gridDim.z selects which of Q/K/V
__global__ __launch_bounds__(256, 2)
void qkv_gemm(const float* __restrict__ X,
              const float* __restrict__ Wq, const float* __restrict__ bq,
              const float* __restrict__ Wk, const float* __restrict__ bk,
              const float* __restrict__ Wv, const float* __restrict__ bv)
{
    const float* W; const float* bias; float* C;
    if (blockIdx.z == 0)      { W = Wq; bias = bq; C = g_Q; }
    else if (blockIdx.z == 1) { W = Wk; bias = bk; C = g_K; }
    else                      { W = Wv; bias = bv; C = g_V; }
    gemm_body(X, W, bias, C);
}

// Output projection: out = g_O @ Wo^T + bo
__global__ __launch_bounds__(256, 2)
void out_gemm(const float* __restrict__ Wo, const float* __restrict__ bo,
              float* __restrict__ out)
{
    gemm_body(g_O, Wo, bo, out);
}

// =====================================================================
// Flash attention (fp32, causal).
// One block = one (b,h) and 128 query rows. 256 threads.
// Inner loop over 64-key tiles: S = Q K^T (staged over HD in 16-chunks),
// online softmax in registers (16-lane shuffle row reductions),
// P staged through smem, O += P V.
// =====================================================================
#define ATTN_SMEM_FLOATS (16*132 + 16*68 + 128*68 + 64*128)
#define ATTN_SMEM_BYTES  (ATTN_SMEM_FLOATS * 4)

__global__ __launch_bounds__(256, 1)
void attn_kernel()
{
    extern __shared__ float sm[];
    float* Qs = sm;                        // [16][132]
    float* Ks = Qs + 16 * 132;             // [16][68]
    float* Ps = Ks + 16 * 68;              // [128][68]
    float* Vs = Ps + 128 * 68;             // [64][128]

    const int tid = threadIdx.x;
    const int tx = tid & 15;               // key/HD column group
    const int ty = tid >> 4;               // query row group
    const int qt = gridDim.x - 1 - blockIdx.x;   // heaviest tiles launch first
    const int q0 = qt * 128;
    const int bh = blockIdx.y;
    const int b  = bh >> 4;
    const int h  = bh & 15;

    const float* Qg = g_Q + (size_t)b * TT * DD + h * HD;
    const float* Kg = g_K + (size_t)b * TT * DD + h * HD;
    const float* Vg = g_V + (size_t)b * TT * DD + h * HD;
    float*       Og = g_O + (size_t)b * TT * DD + h * HD;

    float o[8][8];
    float mrow[8], lrow[8];
#pragma unroll
    for (int i = 0; i < 8; ++i) {
        mrow[i] = -1e30f; lrow[i] = 0.f;
#pragma unroll
        for (int j = 0; j < 8; ++j) o[i][j] = 0.f;
    }

    const int ntiles = q0 / 64 + 2;        // causal: keys 0 .. q0+127
    for (int kt = 0; kt < ntiles; ++kt) {
        const int k0 = kt * 64;
        float s[8][4];
#pragma unroll
        for (int i = 0; i < 8; ++i)
#pragma unroll
            for (int j = 0; j < 4; ++j) s[i][j] = 0.f;

        // ---- GEMM1: S[128][64] = Q(q0:,:) * K(k0:,:)^T over HD=128 ----
        for (int d0 = 0; d0 < HD; d0 += 16) {
            __syncthreads();
            // Q tile 128x16 -> Qs[d][r]
#pragma unroll
            for (int p = tid; p < 512; p += 256) {
                int row = p >> 2, c4 = (p & 3) * 4;
                float4 v = *(const float4*)(Qg + (size_t)(q0 + row) * DD + d0 + c4);
                Qs[(c4 + 0) * 132 + row] = v.x;
                Qs[(c4 + 1) * 132 + row] = v.y;
                Qs[(c4 + 2) * 132 + row] = v.z;
                Qs[(c4 + 3) * 132 + row] = v.w;
            }
            // K tile 64x16 -> Ks[d][k]  (256 float4 slots, 1 per thread)
            {
                int row = tid >> 2, c4 = (tid & 3) * 4;
                float4 v = *(const float4*)(Kg + (size_t)(k0 + row) * DD + d0 + c4);
                Ks[(c4 + 0) * 68 + row] = v.x;
                Ks[(c4 + 1) * 68 + row] = v.y;
                Ks[(c4 + 2) * 68 + row] = v.z;
                Ks[(c4 + 3) * 68 + row] = v.w;
            }
            __syncthreads();
#pragma unroll
            for (int k = 0; k < 16; ++k) {
                float a[8], bb[4];
                *(float4*)(a)     = *(const float4*)&Qs[k * 132 + ty * 8];
                *(float4*)(a + 4) = *(const float4*)&Qs[k * 132 + ty * 8 + 4];
                *(float4*)(bb)    = *(const float4*)&Ks[k * 68 + tx * 4];
#pragma unroll
                for (int i = 0; i < 8; ++i)
#pragma unroll
                    for (int j = 0; j < 4; ++j)
                        s[i][j] += a[i] * bb[j];
            }
        }

        // ---- scale + causal mask + online softmax ----
        const bool need_mask = (k0 + 63 > q0);
        float alpha[8];
#pragma unroll
        for (int i = 0; i < 8; ++i) {
            const int gr = q0 + ty * 8 + i;
            float tm = -1e30f;
#pragma unroll
            for (int j = 0; j < 4; ++j) {
                float v = s[i][j] * SCALE;
                if (need_mask && (k0 + tx * 4 + j > gr)) v = -1e30f;
                s[i][j] = v;
                tm = fmaxf(tm, v);
            }
#pragma unroll
            for (int off = 1; off < 16; off <<= 1)
                tm = fmaxf(tm, __shfl_xor_sync(0xffffffffu, tm, off));
            const float mn = fmaxf(mrow[i], tm);
            const float al = __expf(mrow[i] - mn);
            float rs = 0.f;
#pragma unroll
            for (int j = 0; j < 4; ++j) {
                float p = __expf(s[i][j] - mn);
                s[i][j] = p;
                rs += p;
            }
#pragma unroll
            for (int off = 1; off < 16; off <<= 1)
                rs += __shfl_xor_sync(0xffffffffu, rs, off);
            lrow[i]  = lrow[i] * al + rs;
            mrow[i]  = mn;
            alpha[i] = al;
        }
#pragma unroll
        for (int i = 0; i < 8; ++i)
#pragma unroll
            for (int j = 0; j < 8; ++j)
                o[i][j] *= alpha[i];

        // ---- stage P to smem, load V tile ----
        // WAR on Ps/Vs vs previous tile's GEMM2 is protected by the barriers
        // inside this tile's GEMM1 loop above.
#pragma unroll
        for (int i = 0; i < 8; ++i) {
            float4 pv = make_float4(s[i][0], s[i][1], s[i][2], s[i][3]);
            *(float4*)&Ps[(ty * 8 + i) * 68 + tx * 4] = pv;
        }
#pragma unroll
        for (int p = tid; p < 2048; p += 256) {
            int row = p >> 5, c = (p & 31) * 4;
            float4 v = *(const float4*)(Vg + (size_t)(k0 + row) * DD + c);
            *(float4*)&Vs[row * 128 + c] = v;
        }
        __syncthreads();

        // ---- GEMM2: O[128][128] += P[128][64] * V[64][128] ----
#pragma unroll 4
        for (int kk = 0; kk < 64; ++kk) {
            float a[8];
#pragma unroll
            for (int i = 0; i < 8; ++i) a[i] = Ps[(ty * 8 + i) * 68 + kk];
            float bb[8];
            *(float4*)(bb)     = *(const float4*)&Vs[kk * 128 + tx * 8];
            *(float4*)(bb + 4) = *(const float4*)&Vs[kk * 128 + tx * 8 + 4];
#pragma unroll
            for (int i = 0; i < 8; ++i)
#pragma unroll
                for (int j = 0; j < 8; ++j)
                    o[i][j] += a[i] * bb[j];
        }
    }

    // ---- normalize + write O in [B,T,H,HD] (== [B,T,D]) layout ----
#pragma unroll
    for (int i = 0; i < 8; ++i) {
        const float inv = 1.f / lrow[i];
        const int gr = q0 + ty * 8 + i;
#pragma unroll
        for (int j = 0; j < 8; j += 4) {
            float4 v = make_float4(o[i][j] * inv, o[i][j + 1] * inv,
                                   o[i][j + 2] * inv, o[i][j + 3] * inv);
            *(float4*)(Og + (size_t)gr * DD + tx * 8 + j) = v;
        }
    }
}

// =====================================================================
// Launch
// =====================================================================
extern "C" void kernel_launch(void* const* d_in, const int* in_sizes, int n_in,
                              void* d_out, int out_size)
{
    const float* x  = (const float*)d_in[0];
    // d_in[1] = mask (causal by construction; not needed)
    const float* wq = (const float*)d_in[2];
    const float* bq = (const float*)d_in[3];
    const float* wk = (const float*)d_in[4];
    const float* bk = (const float*)d_in[5];
    const float* wv = (const float*)d_in[6];
    const float* bv = (const float*)d_in[7];
    const float* wo = (const float*)d_in[8];
    const float* bo = (const float*)d_in[9];
    float* out = (float*)d_out;

    // opt-in to >48KB dynamic smem (idempotent, host-side, capture-safe)
    cudaFuncSetAttribute(attn_kernel,
                         cudaFuncAttributeMaxDynamicSharedMemorySize,
                         ATTN_SMEM_BYTES);

    // 1) Q/K/V projections
    dim3 g1(DD / 128, (BB * TT) / 128, 3);
    qkv_gemm<<<g1, 256>>>(x, wq, bq, wk, bk, wv, bv);

    // 2) causal flash attention
    dim3 g2(TT / 128, BB * HH);
    attn_kernel<<<g2, 256, ATTN_SMEM_BYTES>>>();

    // 3) output projection
    dim3 g3(DD / 128, (BB * TT) / 128);
    out_gemm<<<g3, 256>>>(wo, bo, out);
}